// round 7
// baseline (speedup 1.0000x reference)
#include <cuda_runtime.h>
#include <math.h>

#define LLEN 65536
#define BROWS 64
#define CS 32                   /* samples per chunk */
#define PCH (LLEN / CS)         /* 2048 chunks per row */
#define WARMT 64                /* warmup steps */
#define WLIGHT 48               /* light warmup steps */
#define TPB 128                 /* 4 warps per block */
#define NGROUPS 2048            /* 32 row-pairs * 64 groups */
#define NBLOCKS (NGROUPS / 4)   /* 512 */
#define WIN 1088                /* 32*CS + WARMT samples per warp window */

typedef unsigned long long u64;
typedef unsigned int u32;

__device__ __forceinline__ u64 pack2(float lo, float hi) {
    u64 r; asm("mov.b64 %0, {%1, %2};" : "=l"(r) : "f"(lo), "f"(hi)); return r;
}
__device__ __forceinline__ void unpack2(u64 v, float& lo, float& hi) {
    asm("mov.b64 {%0, %1}, %2;" : "=f"(lo), "=f"(hi) : "l"(v));
}
__device__ __forceinline__ u64 fma2(u64 a, u64 b, u64 c) {
    u64 d; asm("fma.rn.f32x2 %0, %1, %2, %3;" : "=l"(d) : "l"(a), "l"(b), "l"(c)); return d;
}
__device__ __forceinline__ u64 add2(u64 a, u64 b) {
    u64 d; asm("add.rn.f32x2 %0, %1, %2;" : "=l"(d) : "l"(a), "l"(b)); return d;
}
__device__ __forceinline__ u64 mul2(u64 a, u64 b) {
    u64 d; asm("mul.rn.f32x2 %0, %1, %2;" : "=l"(d) : "l"(a), "l"(b)); return d;
}
__device__ __forceinline__ u64 tanh2_(u64 v) {
    float lo, hi; unpack2(v, lo, hi);
    float a, b;
    asm("tanh.approx.f32 %0, %1;" : "=f"(a) : "f"(lo));
    asm("tanh.approx.f32 %0, %1;" : "=f"(b) : "f"(hi));
    return pack2(a, b);
}
__device__ __forceinline__ u32 swz(u32 u) { return u ^ ((u >> 5) & 15u); }

struct Cf2 {
    u64 pb0a, pb1a, pb2a, pna1a, pna2a;
    u64 pb0b, pb1b, pb2b, pna1b, pna2b;
    u64 GR1, CRc, GZ1, CZc, HR, HZ, GN1, CNc, MH, MB;
    u64 B0, B1, B2, CC, qna1a, qna2a;
    u64 qb0b, qb1b, qb2b, qna1b, qna2b;
    u64 HALF, NEG1;
};

struct St2 {
    u64 px1a, px2a, py1a, py2a;
    u64 px1b, px2b, py1b, py2b;
    u64 h;
    u64 sh1, sh2, q1y1, q1y2;
    u64 qx1b, qx2b, qy1b, qy2b;
};

__device__ __forceinline__ void step_light2(u64 xi, const Cf2& c, St2& s) {
    u64 ax = fma2(c.pb0a, xi, fma2(c.pb1a, s.px1a, mul2(c.pb2a, s.px2a)));
    u64 v1 = fma2(c.pna1a, s.py1a, fma2(c.pna2a, s.py2a, ax));
    s.px2a = s.px1a; s.px1a = xi; s.py2a = s.py1a; s.py1a = v1;
    u64 bx = fma2(c.pb0b, v1, fma2(c.pb1b, s.px1b, mul2(c.pb2b, s.px2b)));
    u64 v  = fma2(c.pna1b, s.py1b, fma2(c.pna2b, s.py2b, bx));
    s.px2b = s.px1b; s.px1b = v1; s.py2b = s.py1b; s.py1b = v;

    u64 ur = fma2(v, c.GR1, c.CRc);
    u64 uz = fma2(v, c.GZ1, c.CZc);
    u64 Cn = fma2(v, c.GN1, c.CNc);
    u64 tr = fma2(s.h, c.HR, ur);
    u64 tz = fma2(s.h, c.HZ, uz);
    u64 M2 = fma2(s.h, c.MH, c.MB);
    u64 C2 = add2(Cn, M2);
    u64 t_r = tanh2_(tr);
    u64 t_z = tanh2_(tz);
    u64 z   = fma2(c.HALF, t_z, c.HALF);
    u64 sg  = fma2(t_r, M2, C2);
    u64 n   = tanh2_(sg);
    u64 d   = fma2(n, c.NEG1, s.h);        // h - n
    s.h = fma2(z, d, n);                   // n + z*(h-n)
}

__device__ __forceinline__ u64 step_full2(u64 xi, const Cf2& c, St2& s) {
    step_light2(xi, c, s);
    u64 h = s.h;
    u64 a1 = fma2(c.B0, h, fma2(c.B1, s.sh1, fma2(c.B2, s.sh2, c.CC)));
    u64 w1 = fma2(c.qna1a, s.q1y1, fma2(c.qna2a, s.q1y2, a1));
    s.sh2 = s.sh1; s.sh1 = h; s.q1y2 = s.q1y1; s.q1y1 = w1;
    u64 b2x = fma2(c.qb0b, w1, fma2(c.qb1b, s.qx1b, mul2(c.qb2b, s.qx2b)));
    u64 w2  = fma2(c.qna1b, s.qy1b, fma2(c.qna2b, s.qy2b, b2x));
    s.qx2b = s.qx1b; s.qx1b = w1; s.qy2b = s.qy1b; s.qy1b = w2;
    return w2;
}

__global__ void __launch_bounds__(TPB, 3) preamp_kernel(
    const float* __restrict__ x,
    const float* __restrict__ knobs,
    const float* __restrict__ pre_c,
    const float* __restrict__ post_c,
    const float* __restrict__ w_ih,
    const float* __restrict__ w_hh,
    const float* __restrict__ b_ih,
    const float* __restrict__ b_hh,
    const float* __restrict__ w_out,
    const float* __restrict__ b_out,
    const float* __restrict__ kw1,
    const float* __restrict__ kb1,
    const float* __restrict__ kw2,
    const float* __restrict__ kb2,
    float* __restrict__ out)
{
    __shared__ float2 tile[4][WIN];   // per-warp overlapped window, XOR-swizzled

    const int lane = threadIdx.x & 31;
    const int wid  = threadIdx.x >> 5;
    const int G    = blockIdx.x * 4 + wid;   // warp-group 0..2047
    const int rp   = G >> 6;                 // row pair 0..31
    const int gidx = G & 63;                 // group within row (32 chunks each)
    const int row_lo = rp;
    const int row_hi = rp + 32;

    // ---- Knob MLP for both rows ----
    float gains[2], biases[2];
#pragma unroll
    for (int j = 0; j < 2; j++) {
        float kn = knobs[rp + j * 32];
        float acc0 = kb2[0], acc1 = kb2[1];
#pragma unroll
        for (int i = 0; i < 16; i++) {
            float hh = tanhf(fmaf(kn, kw1[i], kb1[i]));
            acc0 = fmaf(hh, kw2[i],      acc0);
            acc1 = fmaf(hh, kw2[16 + i], acc1);
        }
        float p0 = 1.0f / (1.0f + expf(-acc0));
        float p1 = 1.0f / (1.0f + expf(-acc1));
        gains[j]  = expf(fmaf(p0, 4.0f, -2.0f));
        biases[j] = p1 * 0.1f;
    }

    // ---- Pack constants ----
    Cf2 c;
    c.pb0a = pack2(pre_c[0], pre_c[0]);    c.pb1a = pack2(pre_c[1], pre_c[1]);
    c.pb2a = pack2(pre_c[2], pre_c[2]);
    c.pna1a = pack2(-pre_c[3], -pre_c[3]); c.pna2a = pack2(-pre_c[4], -pre_c[4]);
    c.pb0b = pack2(pre_c[5], pre_c[5]);    c.pb1b = pack2(pre_c[6], pre_c[6]);
    c.pb2b = pack2(pre_c[7], pre_c[7]);
    c.pna1b = pack2(-pre_c[8], -pre_c[8]); c.pna2b = pack2(-pre_c[9], -pre_c[9]);
    {
        float wih_r = w_ih[0], wih_z = w_ih[1], wih_n = w_ih[2];
        float whh_r = w_hh[0], whh_z = w_hh[1], whh_n = w_hh[2];
        float cr = b_ih[0] + b_hh[0];
        float cz = b_ih[1] + b_hh[1];
        float gr1[2], crc[2], gz1[2], czc[2], gn1[2], cnc[2];
#pragma unroll
        for (int j = 0; j < 2; j++) {
            gr1[j] = 0.5f * wih_r * gains[j]; crc[j] = 0.5f * fmaf(wih_r, biases[j], cr);
            gz1[j] = 0.5f * wih_z * gains[j]; czc[j] = 0.5f * fmaf(wih_z, biases[j], cz);
            gn1[j] = wih_n * gains[j];        cnc[j] = fmaf(wih_n, biases[j], b_ih[2]);
        }
        c.GR1 = pack2(gr1[0], gr1[1]); c.CRc = pack2(crc[0], crc[1]);
        c.GZ1 = pack2(gz1[0], gz1[1]); c.CZc = pack2(czc[0], czc[1]);
        c.GN1 = pack2(gn1[0], gn1[1]); c.CNc = pack2(cnc[0], cnc[1]);
        c.HR = pack2(0.5f * whh_r, 0.5f * whh_r);
        c.HZ = pack2(0.5f * whh_z, 0.5f * whh_z);
        c.MH = pack2(0.5f * whh_n, 0.5f * whh_n);
        c.MB = pack2(0.5f * b_hh[2], 0.5f * b_hh[2]);
    }
    {
        float wout = w_out[0], bout = b_out[0];
        float b0 = post_c[0] * wout, b1 = post_c[1] * wout, b2v = post_c[2] * wout;
        float cc = bout * (post_c[0] + post_c[1] + post_c[2]);
        c.B0 = pack2(b0, b0); c.B1 = pack2(b1, b1); c.B2 = pack2(b2v, b2v);
        c.CC = pack2(cc, cc);
        c.qna1a = pack2(-post_c[3], -post_c[3]); c.qna2a = pack2(-post_c[4], -post_c[4]);
        c.qb0b = pack2(post_c[5], post_c[5]);    c.qb1b = pack2(post_c[6], post_c[6]);
        c.qb2b = pack2(post_c[7], post_c[7]);
        c.qna1b = pack2(-post_c[8], -post_c[8]); c.qna2b = pack2(-post_c[9], -post_c[9]);
    }
    c.HALF = pack2(0.5f, 0.5f);
    c.NEG1 = pack2(-1.0f, -1.0f);

    St2 s;
    s.px1a = s.px2a = s.py1a = s.py2a = 0ull;
    s.px1b = s.px2b = s.py1b = s.py2b = 0ull;
    s.h = 0ull;
    s.sh1 = s.sh2 = s.q1y1 = s.q1y2 = 0ull;
    s.qx1b = s.qx2b = s.qy1b = s.qy2b = 0ull;

    if (gidx != 0) {
        // ============ FAST PATH: swizzled smem window ============
        const int base = gidx * 1024 - WARMT;    // >= 960, 16-aligned
        const float4* xlo4 = (const float4*)(x + (size_t)row_lo * LLEN + base);
        const float4* xhi4 = (const float4*)(x + (size_t)row_hi * LLEN + base);
        float2* tl = tile[wid];
        for (int i = lane; i < WIN / 4; i += 32) {
            float4 a = __ldg(xlo4 + i);
            float4 b = __ldg(xhi4 + i);
            u32 u = (u32)(i * 4);
            tl[swz(u + 0)] = make_float2(a.x, b.x);
            tl[swz(u + 1)] = make_float2(a.y, b.y);
            tl[swz(u + 2)] = make_float2(a.z, b.z);
            tl[swz(u + 3)] = make_float2(a.w, b.w);
        }
        __syncwarp();

        const u32 ub = 32u * lane;

#pragma unroll 8
        for (int k = 0; k < WLIGHT; k++) {
            u64 xi = reinterpret_cast<const u64&>(tl[swz(ub + k)]);
            step_light2(xi, c, s);
        }
#pragma unroll 8
        for (int k = WLIGHT; k < WARMT; k++) {
            u64 xi = reinterpret_cast<const u64&>(tl[swz(ub + k)]);
            step_full2(xi, c, s);
        }

        const size_t t0 = (size_t)(gidx * 32 + lane) * CS;
        float4* ovlo = (float4*)(out + (size_t)row_lo * LLEN + t0);
        float4* ovhi = (float4*)(out + (size_t)row_hi * LLEN + t0);
        float ol[4], oh[4];
#pragma unroll 8
        for (int k = WARMT; k < WARMT + CS; k++) {
            u64 xi = reinterpret_cast<const u64&>(tl[swz(ub + k)]);
            u64 w2 = step_full2(xi, c, s);
            int m = k & 3;
            unpack2(w2, ol[m], oh[m]);
            if (m == 3) {
                ovlo[(k - WARMT) >> 2] = make_float4(ol[0], ol[1], ol[2], ol[3]);
                ovhi[(k - WARMT) >> 2] = make_float4(oh[0], oh[1], oh[2], oh[3]);
            }
        }
    } else {
        // ============ SLOW PATH: first 32 chunks of each row pair ============
        const int t0 = lane * CS;
        const int s0 = (t0 > WARMT) ? (t0 - WARMT) : 0;
        const int f0 = (t0 > (WARMT - WLIGHT)) ? (t0 - (WARMT - WLIGHT)) : 0;
        const float4* xl4 = (const float4*)(x + (size_t)row_lo * LLEN);
        const float4* xh4 = (const float4*)(x + (size_t)row_hi * LLEN);

        for (int q = s0 / 4; q < f0 / 4; q++) {
            float4 a = __ldg(xl4 + q), b = __ldg(xh4 + q);
            step_light2(pack2(a.x, b.x), c, s);
            step_light2(pack2(a.y, b.y), c, s);
            step_light2(pack2(a.z, b.z), c, s);
            step_light2(pack2(a.w, b.w), c, s);
        }
        for (int q = f0 / 4; q < t0 / 4; q++) {
            float4 a = __ldg(xl4 + q), b = __ldg(xh4 + q);
            step_full2(pack2(a.x, b.x), c, s);
            step_full2(pack2(a.y, b.y), c, s);
            step_full2(pack2(a.z, b.z), c, s);
            step_full2(pack2(a.w, b.w), c, s);
        }
        float4* ovlo = (float4*)(out + (size_t)row_lo * LLEN + t0);
        float4* ovhi = (float4*)(out + (size_t)row_hi * LLEN + t0);
        for (int q = t0 / 4, j = 0; q < (t0 + CS) / 4; q++, j++) {
            float4 a = __ldg(xl4 + q), b = __ldg(xh4 + q);
            float4 olo, ohi;
            u64 w;
            w = step_full2(pack2(a.x, b.x), c, s); unpack2(w, olo.x, ohi.x);
            w = step_full2(pack2(a.y, b.y), c, s); unpack2(w, olo.y, ohi.y);
            w = step_full2(pack2(a.z, b.z), c, s); unpack2(w, olo.z, ohi.z);
            w = step_full2(pack2(a.w, b.w), c, s); unpack2(w, olo.w, ohi.w);
            ovlo[j] = olo;
            ovhi[j] = ohi;
        }
    }
}

extern "C" void kernel_launch(void* const* d_in, const int* in_sizes, int n_in,
                              void* d_out, int out_size) {
    (void)in_sizes; (void)n_in; (void)out_size;
    preamp_kernel<<<NBLOCKS, TPB>>>(
        (const float*)d_in[0],  (const float*)d_in[1],  (const float*)d_in[2],
        (const float*)d_in[3],  (const float*)d_in[4],  (const float*)d_in[5],
        (const float*)d_in[6],  (const float*)d_in[7],  (const float*)d_in[8],
        (const float*)d_in[9],  (const float*)d_in[10], (const float*)d_in[11],
        (const float*)d_in[12], (const float*)d_in[13], (float*)d_out);
}

// round 8
// speedup vs baseline: 1.4247x; 1.4247x over previous
#include <cuda_runtime.h>
#include <math.h>

#define LLEN 65536
#define BROWS 64
#define CS 32                   /* samples per chunk */
#define PCH (LLEN / CS)         /* 2048 chunks per row */
#define WARMT 32                /* warmup steps */
#define WLIGHT 16               /* light warmup steps */
#define TPB 128                 /* 4 warps per block */
#define NGROUPS 2048            /* 32 row-pairs * 64 groups */
#define NBLOCKS (NGROUPS / 4)   /* 512 */
#define UNION 1056              /* 32*CS + WARMT samples per warp window */
#define TILE_SZ 1088            /* padded: +1 float2 per 32 */

typedef unsigned long long u64;
typedef unsigned int u32;

__device__ __forceinline__ u64 pack2(float lo, float hi) {
    u64 r; asm("mov.b64 %0, {%1, %2};" : "=l"(r) : "f"(lo), "f"(hi)); return r;
}
__device__ __forceinline__ void unpack2(u64 v, float& lo, float& hi) {
    asm("mov.b64 {%0, %1}, %2;" : "=f"(lo), "=f"(hi) : "l"(v));
}
__device__ __forceinline__ u64 fma2(u64 a, u64 b, u64 c) {
    u64 d; asm("fma.rn.f32x2 %0, %1, %2, %3;" : "=l"(d) : "l"(a), "l"(b), "l"(c)); return d;
}
__device__ __forceinline__ u64 add2(u64 a, u64 b) {
    u64 d; asm("add.rn.f32x2 %0, %1, %2;" : "=l"(d) : "l"(a), "l"(b)); return d;
}
__device__ __forceinline__ u64 sub2(u64 a, u64 b) {
    u64 d; asm("sub.rn.f32x2 %0, %1, %2;" : "=l"(d) : "l"(a), "l"(b)); return d;
}
__device__ __forceinline__ u64 mul2(u64 a, u64 b) {
    u64 d; asm("mul.rn.f32x2 %0, %1, %2;" : "=l"(d) : "l"(a), "l"(b)); return d;
}
__device__ __forceinline__ u64 tanh2_(u64 v) {
    float lo, hi; unpack2(v, lo, hi);
    float a, b;
    asm("tanh.approx.f32 %0, %1;" : "=f"(a) : "f"(lo));
    asm("tanh.approx.f32 %0, %1;" : "=f"(b) : "f"(hi));
    return pack2(a, b);
}

struct Cf2 {
    u64 pb0a, pb1a, pb2a, pna1a, pna2a;
    u64 pb0b, pb1b, pb2b, pna1b, pna2b;
    u64 GR1, CRc, GZ1, CZc, HR, HZ, GN1, CNc, MH, MB;
    u64 B0, B1, B2, CC, qna1a, qna2a;
    u64 qb0b, qb1b, qb2b, qna1b, qna2b;
    u64 HALF;
};

// DF-II-transposed state: 2 regs per biquad; post1 s1 init = CC.
struct St2 {
    u64 a1, a2;      // pre bq1
    u64 b1, b2;      // pre bq2
    u64 h;           // GRU
    u64 c1, c2;      // post bq1 (w_out folded)
    u64 d1, d2;      // post bq2
};

// DF-II-T biquad: y = b0*x + s1; s1' = b1*x + s2 - a1*y; s2' = b2*x - a2*y
__device__ __forceinline__ u64 bq(u64 x, u64 b0, u64 b1, u64 b2,
                                  u64 na1, u64 na2, u64& s1, u64& s2) {
    u64 y = fma2(b0, x, s1);
    s1 = fma2(na1, y, fma2(b1, x, s2));
    s2 = fma2(na2, y, mul2(b2, x));
    return y;
}

__device__ __forceinline__ void step_light2(u64 xi, const Cf2& c, St2& s) {
    u64 v1 = bq(xi, c.pb0a, c.pb1a, c.pb2a, c.pna1a, c.pna2a, s.a1, s.a2);
    u64 v  = bq(v1, c.pb0b, c.pb1b, c.pb2b, c.pna1b, c.pna2b, s.b1, s.b2);

    u64 ur = fma2(v, c.GR1, c.CRc);
    u64 uz = fma2(v, c.GZ1, c.CZc);
    u64 Cn = fma2(v, c.GN1, c.CNc);
    u64 tr = fma2(s.h, c.HR, ur);
    u64 tz = fma2(s.h, c.HZ, uz);
    u64 M2 = fma2(s.h, c.MH, c.MB);
    u64 C2 = add2(Cn, M2);
    u64 t_r = tanh2_(tr);
    u64 t_z = tanh2_(tz);
    u64 z   = fma2(c.HALF, t_z, c.HALF);
    u64 sg  = fma2(t_r, M2, C2);
    u64 n   = tanh2_(sg);
    u64 d   = sub2(s.h, n);
    s.h = fma2(z, d, n);
}

__device__ __forceinline__ u64 step_full2(u64 xi, const Cf2& c, St2& s) {
    step_light2(xi, c, s);
    u64 h = s.h;
    // post stage 1 with per-step bias CC re-injected into s1
    u64 w1 = fma2(c.B0, h, s.c1);
    s.c1 = fma2(c.qna1a, w1, fma2(c.B1, h, add2(s.c2, c.CC)));
    s.c2 = fma2(c.qna2a, w1, mul2(c.B2, h));
    // post stage 2
    u64 w2 = bq(w1, c.qb0b, c.qb1b, c.qb2b, c.qna1b, c.qna2b, s.d1, s.d2);
    return w2;
}

__global__ void __launch_bounds__(TPB, 4) preamp_kernel(
    const float* __restrict__ x,
    const float* __restrict__ knobs,
    const float* __restrict__ pre_c,
    const float* __restrict__ post_c,
    const float* __restrict__ w_ih,
    const float* __restrict__ w_hh,
    const float* __restrict__ b_ih,
    const float* __restrict__ b_hh,
    const float* __restrict__ w_out,
    const float* __restrict__ b_out,
    const float* __restrict__ kw1,
    const float* __restrict__ kb1,
    const float* __restrict__ kw2,
    const float* __restrict__ kb2,
    float* __restrict__ out)
{
    __shared__ float2 tile[4][TILE_SZ];   // per-warp shared union window

    const int lane = threadIdx.x & 31;
    const int wid  = threadIdx.x >> 5;
    const int G    = blockIdx.x * 4 + wid;   // warp-group 0..2047
    const int rp   = G >> 6;                 // row pair 0..31
    const int gidx = G & 63;                 // group within row
    const int row_lo = rp;
    const int row_hi = rp + 32;

    // ---- Knob MLP for both rows ----
    float gains[2], biases[2];
#pragma unroll
    for (int j = 0; j < 2; j++) {
        float kn = knobs[rp + j * 32];
        float acc0 = kb2[0], acc1 = kb2[1];
#pragma unroll
        for (int i = 0; i < 16; i++) {
            float hh = tanhf(fmaf(kn, kw1[i], kb1[i]));
            acc0 = fmaf(hh, kw2[i],      acc0);
            acc1 = fmaf(hh, kw2[16 + i], acc1);
        }
        float p0 = 1.0f / (1.0f + expf(-acc0));
        float p1 = 1.0f / (1.0f + expf(-acc1));
        gains[j]  = expf(fmaf(p0, 4.0f, -2.0f));
        biases[j] = p1 * 0.1f;
    }

    // ---- Pack constants ----
    Cf2 c;
    c.pb0a = pack2(pre_c[0], pre_c[0]);    c.pb1a = pack2(pre_c[1], pre_c[1]);
    c.pb2a = pack2(pre_c[2], pre_c[2]);
    c.pna1a = pack2(-pre_c[3], -pre_c[3]); c.pna2a = pack2(-pre_c[4], -pre_c[4]);
    c.pb0b = pack2(pre_c[5], pre_c[5]);    c.pb1b = pack2(pre_c[6], pre_c[6]);
    c.pb2b = pack2(pre_c[7], pre_c[7]);
    c.pna1b = pack2(-pre_c[8], -pre_c[8]); c.pna2b = pack2(-pre_c[9], -pre_c[9]);
    {
        float wih_r = w_ih[0], wih_z = w_ih[1], wih_n = w_ih[2];
        float whh_r = w_hh[0], whh_z = w_hh[1], whh_n = w_hh[2];
        float cr = b_ih[0] + b_hh[0];
        float cz = b_ih[1] + b_hh[1];
        float gr1[2], crc[2], gz1[2], czc[2], gn1[2], cnc[2];
#pragma unroll
        for (int j = 0; j < 2; j++) {
            gr1[j] = 0.5f * wih_r * gains[j]; crc[j] = 0.5f * fmaf(wih_r, biases[j], cr);
            gz1[j] = 0.5f * wih_z * gains[j]; czc[j] = 0.5f * fmaf(wih_z, biases[j], cz);
            gn1[j] = wih_n * gains[j];        cnc[j] = fmaf(wih_n, biases[j], b_ih[2]);
        }
        c.GR1 = pack2(gr1[0], gr1[1]); c.CRc = pack2(crc[0], crc[1]);
        c.GZ1 = pack2(gz1[0], gz1[1]); c.CZc = pack2(czc[0], czc[1]);
        c.GN1 = pack2(gn1[0], gn1[1]); c.CNc = pack2(cnc[0], cnc[1]);
        c.HR = pack2(0.5f * whh_r, 0.5f * whh_r);
        c.HZ = pack2(0.5f * whh_z, 0.5f * whh_z);
        c.MH = pack2(0.5f * whh_n, 0.5f * whh_n);
        c.MB = pack2(0.5f * b_hh[2], 0.5f * b_hh[2]);
    }
    {
        float wout = w_out[0], bout = b_out[0];
        float b0 = post_c[0] * wout, b1 = post_c[1] * wout, b2v = post_c[2] * wout;
        float cc = bout * (post_c[0] + post_c[1] + post_c[2]);
        c.B0 = pack2(b0, b0); c.B1 = pack2(b1, b1); c.B2 = pack2(b2v, b2v);
        c.CC = pack2(cc, cc);
        c.qna1a = pack2(-post_c[3], -post_c[3]); c.qna2a = pack2(-post_c[4], -post_c[4]);
        c.qb0b = pack2(post_c[5], post_c[5]);    c.qb1b = pack2(post_c[6], post_c[6]);
        c.qb2b = pack2(post_c[7], post_c[7]);
        c.qna1b = pack2(-post_c[8], -post_c[8]); c.qna2b = pack2(-post_c[9], -post_c[9]);
    }
    c.HALF = pack2(0.5f, 0.5f);

    St2 s;
    s.a1 = s.a2 = s.b1 = s.b2 = 0ull;
    s.h = 0ull;
    s.c1 = c.CC; s.c2 = 0ull;       // post1 s1 init = CC
    s.d1 = s.d2 = 0ull;

    if (gidx != 0) {
        // ============ FAST PATH: shared union window, static addressing ============
        const int base = gidx * 1024 - WARMT;    // >= 992, 16-aligned
        const float4* xlo4 = (const float4*)(x + (size_t)row_lo * LLEN + base);
        const float4* xhi4 = (const float4*)(x + (size_t)row_hi * LLEN + base);
        float2* tl = tile[wid];
#pragma unroll
        for (int rep = 0; rep < UNION / 128; rep++) {     // 264 float4 / 32 lanes
            int i = rep * 32 + lane;
            float4 a = __ldg(xlo4 + i);
            float4 b = __ldg(xhi4 + i);
            int p = i * 4;
            int q = p + (p >> 5);                          // +1 float2 pad per 32
            tl[q + 0] = make_float2(a.x, b.x);
            tl[q + 1] = make_float2(a.y, b.y);
            tl[q + 2] = make_float2(a.z, b.z);
            tl[q + 3] = make_float2(a.w, b.w);
        }
        {   // remainder: 264 = 8*32 + 8 -> lanes 0..7 do one more
            int i = 8 * 32 + lane;
            if (lane < 8) {
                float4 a = __ldg(xlo4 + i);
                float4 b = __ldg(xhi4 + i);
                int p = i * 4;
                int q = p + (p >> 5);
                tl[q + 0] = make_float2(a.x, b.x);
                tl[q + 1] = make_float2(a.y, b.y);
                tl[q + 2] = make_float2(a.z, b.z);
                tl[q + 3] = make_float2(a.w, b.w);
            }
        }
        __syncwarp();

        // per-lane window: samples [32*lane, 32*lane+64), padded loc = 33*lane + k + (k>>5)
        const float2* lw = tl + 33 * lane;

#pragma unroll 8
        for (int k = 0; k < WLIGHT; k++) {               // k < 32: k>>5 == 0
            u64 xi = reinterpret_cast<const u64&>(lw[k]);
            step_light2(xi, c, s);
        }
#pragma unroll 8
        for (int k = WLIGHT; k < WARMT; k++) {
            u64 xi = reinterpret_cast<const u64&>(lw[k]);
            step_full2(xi, c, s);
        }

        const size_t t0 = (size_t)(gidx * 32 + lane) * CS;
        float4* ovlo = (float4*)(out + (size_t)row_lo * LLEN + t0);
        float4* ovhi = (float4*)(out + (size_t)row_hi * LLEN + t0);
        float ol[4], oh[4];
#pragma unroll 8
        for (int k = WARMT; k < WARMT + CS; k++) {       // k in [32,64): k>>5 == 1
            u64 xi = reinterpret_cast<const u64&>(lw[k + 1]);
            u64 w2 = step_full2(xi, c, s);
            int m = k & 3;
            unpack2(w2, ol[m], oh[m]);
            if (m == 3) {
                ovlo[(k - WARMT) >> 2] = make_float4(ol[0], ol[1], ol[2], ol[3]);
                ovhi[(k - WARMT) >> 2] = make_float4(oh[0], oh[1], oh[2], oh[3]);
            }
        }
    } else {
        // ============ SLOW PATH: first 32 chunks of each row pair ============
        const int t0 = lane * CS;
        const int s0 = (t0 > WARMT) ? (t0 - WARMT) : 0;
        const int f0 = (t0 > (WARMT - WLIGHT)) ? (t0 - (WARMT - WLIGHT)) : 0;
        const float4* xl4 = (const float4*)(x + (size_t)row_lo * LLEN);
        const float4* xh4 = (const float4*)(x + (size_t)row_hi * LLEN);

        for (int q = s0 / 4; q < f0 / 4; q++) {
            float4 a = __ldg(xl4 + q), b = __ldg(xh4 + q);
            step_light2(pack2(a.x, b.x), c, s);
            step_light2(pack2(a.y, b.y), c, s);
            step_light2(pack2(a.z, b.z), c, s);
            step_light2(pack2(a.w, b.w), c, s);
        }
        for (int q = f0 / 4; q < t0 / 4; q++) {
            float4 a = __ldg(xl4 + q), b = __ldg(xh4 + q);
            step_full2(pack2(a.x, b.x), c, s);
            step_full2(pack2(a.y, b.y), c, s);
            step_full2(pack2(a.z, b.z), c, s);
            step_full2(pack2(a.w, b.w), c, s);
        }
        float4* ovlo = (float4*)(out + (size_t)row_lo * LLEN + t0);
        float4* ovhi = (float4*)(out + (size_t)row_hi * LLEN + t0);
        for (int q = t0 / 4, j = 0; q < (t0 + CS) / 4; q++, j++) {
            float4 a = __ldg(xl4 + q), b = __ldg(xh4 + q);
            float4 olo, ohi;
            u64 w;
            w = step_full2(pack2(a.x, b.x), c, s); unpack2(w, olo.x, ohi.x);
            w = step_full2(pack2(a.y, b.y), c, s); unpack2(w, olo.y, ohi.y);
            w = step_full2(pack2(a.z, b.z), c, s); unpack2(w, olo.z, ohi.z);
            w = step_full2(pack2(a.w, b.w), c, s); unpack2(w, olo.w, ohi.w);
            ovlo[j] = olo;
            ovhi[j] = ohi;
        }
    }
}

extern "C" void kernel_launch(void* const* d_in, const int* in_sizes, int n_in,
                              void* d_out, int out_size) {
    (void)in_sizes; (void)n_in; (void)out_size;
    preamp_kernel<<<NBLOCKS, TPB>>>(
        (const float*)d_in[0],  (const float*)d_in[1],  (const float*)d_in[2],
        (const float*)d_in[3],  (const float*)d_in[4],  (const float*)d_in[5],
        (const float*)d_in[6],  (const float*)d_in[7],  (const float*)d_in[8],
        (const float*)d_in[9],  (const float*)d_in[10], (const float*)d_in[11],
        (const float*)d_in[12], (const float*)d_in[13], (float*)d_out);
}

// round 9
// speedup vs baseline: 1.5600x; 1.0950x over previous
#include <cuda_runtime.h>
#include <math.h>

#define LLEN 65536
#define BROWS 64
#define CS 32                   /* samples per chunk */
#define WARMT 16                /* warmup steps */
#define WLIGHT 8                /* light warmup steps */
#define TPB 128                 /* 4 warps per block */
#define NGROUPS 2048            /* 32 row-pairs * 64 groups */
#define NBLOCKS (NGROUPS / 4)   /* 512 */
#define UNION 1040              /* 32*CS + WARMT samples per warp window */
#define TILE_SZ 1104            /* padded: +2 float2 per 32 samples */

typedef unsigned long long u64;

__device__ __forceinline__ u64 pack2(float lo, float hi) {
    u64 r; asm("mov.b64 %0, {%1, %2};" : "=l"(r) : "f"(lo), "f"(hi)); return r;
}
__device__ __forceinline__ void unpack2(u64 v, float& lo, float& hi) {
    asm("mov.b64 {%0, %1}, %2;" : "=f"(lo), "=f"(hi) : "l"(v));
}
__device__ __forceinline__ u64 fma2(u64 a, u64 b, u64 c) {
    u64 d; asm("fma.rn.f32x2 %0, %1, %2, %3;" : "=l"(d) : "l"(a), "l"(b), "l"(c)); return d;
}
__device__ __forceinline__ u64 add2(u64 a, u64 b) {
    u64 d; asm("add.rn.f32x2 %0, %1, %2;" : "=l"(d) : "l"(a), "l"(b)); return d;
}
__device__ __forceinline__ u64 sub2(u64 a, u64 b) {
    u64 d; asm("sub.rn.f32x2 %0, %1, %2;" : "=l"(d) : "l"(a), "l"(b)); return d;
}
__device__ __forceinline__ u64 mul2(u64 a, u64 b) {
    u64 d; asm("mul.rn.f32x2 %0, %1, %2;" : "=l"(d) : "l"(a), "l"(b)); return d;
}
__device__ __forceinline__ u64 tanh2_(u64 v) {
    float lo, hi; unpack2(v, lo, hi);
    float a, b;
    asm("tanh.approx.f32 %0, %1;" : "=f"(a) : "f"(lo));
    asm("tanh.approx.f32 %0, %1;" : "=f"(b) : "f"(hi));
    return pack2(a, b);
}

struct Cf2 {
    u64 pb0a, pb1a, pb2a, pna1a, pna2a;
    u64 pb0b, pb1b, pb2b, pna1b, pna2b;
    u64 GR1, CRc, GZ1, CZc, HR, HZ, GN1, CNc, MH, MB;
    u64 B0, B1, B2, CC, qna1a, qna2a;
    u64 qb0b, qb1b, qb2b, qna1b, qna2b;
    u64 HALF;
};

// DF-II-transposed state: 2 regs per biquad.
struct St2 {
    u64 a1, a2;      // pre bq1
    u64 b1, b2;      // pre bq2
    u64 h;           // GRU
    u64 c1, c2;      // post bq1 (w_out folded; CC re-injected per step)
    u64 d1, d2;      // post bq2
};

__device__ __forceinline__ u64 bq(u64 x, u64 b0, u64 b1, u64 b2,
                                  u64 na1, u64 na2, u64& s1, u64& s2) {
    u64 y = fma2(b0, x, s1);
    s1 = fma2(na1, y, fma2(b1, x, s2));
    s2 = fma2(na2, y, mul2(b2, x));
    return y;
}

__device__ __forceinline__ void step_light2(u64 xi, const Cf2& c, St2& s) {
    u64 v1 = bq(xi, c.pb0a, c.pb1a, c.pb2a, c.pna1a, c.pna2a, s.a1, s.a2);
    u64 v  = bq(v1, c.pb0b, c.pb1b, c.pb2b, c.pna1b, c.pna2b, s.b1, s.b2);

    u64 ur = fma2(v, c.GR1, c.CRc);
    u64 uz = fma2(v, c.GZ1, c.CZc);
    u64 Cn = fma2(v, c.GN1, c.CNc);
    u64 tr = fma2(s.h, c.HR, ur);
    u64 tz = fma2(s.h, c.HZ, uz);
    u64 M2 = fma2(s.h, c.MH, c.MB);
    u64 C2 = add2(Cn, M2);
    u64 t_r = tanh2_(tr);
    u64 t_z = tanh2_(tz);
    u64 z   = fma2(c.HALF, t_z, c.HALF);
    u64 sg  = fma2(t_r, M2, C2);
    u64 n   = tanh2_(sg);
    u64 d   = sub2(s.h, n);
    s.h = fma2(z, d, n);
}

__device__ __forceinline__ u64 step_full2(u64 xi, const Cf2& c, St2& s) {
    step_light2(xi, c, s);
    u64 h = s.h;
    u64 w1 = fma2(c.B0, h, s.c1);
    s.c1 = fma2(c.qna1a, w1, fma2(c.B1, h, add2(s.c2, c.CC)));
    s.c2 = fma2(c.qna2a, w1, mul2(c.B2, h));
    u64 w2 = bq(w1, c.qb0b, c.qb1b, c.qb2b, c.qna1b, c.qna2b, s.d1, s.d2);
    return w2;
}

__global__ void __launch_bounds__(TPB, 4) preamp_kernel(
    const float* __restrict__ x,
    const float* __restrict__ knobs,
    const float* __restrict__ pre_c,
    const float* __restrict__ post_c,
    const float* __restrict__ w_ih,
    const float* __restrict__ w_hh,
    const float* __restrict__ b_ih,
    const float* __restrict__ b_hh,
    const float* __restrict__ w_out,
    const float* __restrict__ b_out,
    const float* __restrict__ kw1,
    const float* __restrict__ kb1,
    const float* __restrict__ kw2,
    const float* __restrict__ kb2,
    float* __restrict__ out)
{
    __shared__ __align__(16) float2 tile[4][TILE_SZ];   // per-warp shared union window

    const int lane = threadIdx.x & 31;
    const int wid  = threadIdx.x >> 5;
    const int G    = blockIdx.x * 4 + wid;   // warp-group 0..2047
    const int rp   = G >> 6;                 // row pair 0..31
    const int gidx = G & 63;                 // group within row
    const int row_lo = rp;
    const int row_hi = rp + 32;

    // ---- Knob MLP for both rows ----
    float gains[2], biases[2];
#pragma unroll
    for (int j = 0; j < 2; j++) {
        float kn = knobs[rp + j * 32];
        float acc0 = kb2[0], acc1 = kb2[1];
#pragma unroll
        for (int i = 0; i < 16; i++) {
            float hh = tanhf(fmaf(kn, kw1[i], kb1[i]));
            acc0 = fmaf(hh, kw2[i],      acc0);
            acc1 = fmaf(hh, kw2[16 + i], acc1);
        }
        float p0 = 1.0f / (1.0f + expf(-acc0));
        float p1 = 1.0f / (1.0f + expf(-acc1));
        gains[j]  = expf(fmaf(p0, 4.0f, -2.0f));
        biases[j] = p1 * 0.1f;
    }

    // ---- Pack constants ----
    Cf2 c;
    c.pb0a = pack2(pre_c[0], pre_c[0]);    c.pb1a = pack2(pre_c[1], pre_c[1]);
    c.pb2a = pack2(pre_c[2], pre_c[2]);
    c.pna1a = pack2(-pre_c[3], -pre_c[3]); c.pna2a = pack2(-pre_c[4], -pre_c[4]);
    c.pb0b = pack2(pre_c[5], pre_c[5]);    c.pb1b = pack2(pre_c[6], pre_c[6]);
    c.pb2b = pack2(pre_c[7], pre_c[7]);
    c.pna1b = pack2(-pre_c[8], -pre_c[8]); c.pna2b = pack2(-pre_c[9], -pre_c[9]);
    {
        float wih_r = w_ih[0], wih_z = w_ih[1], wih_n = w_ih[2];
        float whh_r = w_hh[0], whh_z = w_hh[1], whh_n = w_hh[2];
        float cr = b_ih[0] + b_hh[0];
        float cz = b_ih[1] + b_hh[1];
        float gr1[2], crc[2], gz1[2], czc[2], gn1[2], cnc[2];
#pragma unroll
        for (int j = 0; j < 2; j++) {
            gr1[j] = 0.5f * wih_r * gains[j]; crc[j] = 0.5f * fmaf(wih_r, biases[j], cr);
            gz1[j] = 0.5f * wih_z * gains[j]; czc[j] = 0.5f * fmaf(wih_z, biases[j], cz);
            gn1[j] = wih_n * gains[j];        cnc[j] = fmaf(wih_n, biases[j], b_ih[2]);
        }
        c.GR1 = pack2(gr1[0], gr1[1]); c.CRc = pack2(crc[0], crc[1]);
        c.GZ1 = pack2(gz1[0], gz1[1]); c.CZc = pack2(czc[0], czc[1]);
        c.GN1 = pack2(gn1[0], gn1[1]); c.CNc = pack2(cnc[0], cnc[1]);
        c.HR = pack2(0.5f * whh_r, 0.5f * whh_r);
        c.HZ = pack2(0.5f * whh_z, 0.5f * whh_z);
        c.MH = pack2(0.5f * whh_n, 0.5f * whh_n);
        c.MB = pack2(0.5f * b_hh[2], 0.5f * b_hh[2]);
    }
    {
        float wout = w_out[0], bout = b_out[0];
        float b0 = post_c[0] * wout, b1 = post_c[1] * wout, b2v = post_c[2] * wout;
        float cc = bout * (post_c[0] + post_c[1] + post_c[2]);
        c.B0 = pack2(b0, b0); c.B1 = pack2(b1, b1); c.B2 = pack2(b2v, b2v);
        c.CC = pack2(cc, cc);
        c.qna1a = pack2(-post_c[3], -post_c[3]); c.qna2a = pack2(-post_c[4], -post_c[4]);
        c.qb0b = pack2(post_c[5], post_c[5]);    c.qb1b = pack2(post_c[6], post_c[6]);
        c.qb2b = pack2(post_c[7], post_c[7]);
        c.qna1b = pack2(-post_c[8], -post_c[8]); c.qna2b = pack2(-post_c[9], -post_c[9]);
    }
    c.HALF = pack2(0.5f, 0.5f);

    St2 s;
    s.a1 = s.a2 = s.b1 = s.b2 = 0ull;
    s.h = 0ull;
    s.c1 = c.CC; s.c2 = 0ull;
    s.d1 = s.d2 = 0ull;

    if (gidx != 0) {
        // ============ FAST PATH ============
        const int base = gidx * 1024 - WARMT;
        const float4* xlo4 = (const float4*)(x + (size_t)row_lo * LLEN + base);
        const float4* xhi4 = (const float4*)(x + (size_t)row_hi * LLEN + base);
        float2* tl = tile[wid];
        // UNION/4 = 260 float4 = 8*32 + 4
#pragma unroll
        for (int rep = 0; rep < 8; rep++) {
            int i = rep * 32 + lane;
            float4 a = __ldg(xlo4 + i);
            float4 b = __ldg(xhi4 + i);
            int p = i * 4;
            int q = p + 2 * (p >> 5);           // +2 float2 per 32 samples
            tl[q + 0] = make_float2(a.x, b.x);
            tl[q + 1] = make_float2(a.y, b.y);
            tl[q + 2] = make_float2(a.z, b.z);
            tl[q + 3] = make_float2(a.w, b.w);
        }
        if (lane < 4) {
            int i = 256 + lane;
            float4 a = __ldg(xlo4 + i);
            float4 b = __ldg(xhi4 + i);
            int p = i * 4;
            int q = p + 2 * (p >> 5);
            tl[q + 0] = make_float2(a.x, b.x);
            tl[q + 1] = make_float2(a.y, b.y);
            tl[q + 2] = make_float2(a.z, b.z);
            tl[q + 3] = make_float2(a.w, b.w);
        }
        __syncwarp();

        // Per-lane window: samples [32*lane, 32*lane+48).
        // float2 idx = 34*lane + k + 2*(k>>5); 16B-aligned base -> LDS.128 pairs.
        const float4* lw = reinterpret_cast<const float4*>(tl + 34 * lane);

        // warmup light: k=0..7 (j = k/2)
#pragma unroll
        for (int j = 0; j < 4; j++) {
            float4 f = lw[j];
            step_light2(pack2(f.x, f.y), c, s);
            step_light2(pack2(f.z, f.w), c, s);
        }
        // warmup full: k=8..15
#pragma unroll
        for (int j = 4; j < 8; j++) {
            float4 f = lw[j];
            step_full2(pack2(f.x, f.y), c, s);
            step_full2(pack2(f.z, f.w), c, s);
        }

        const size_t t0 = (size_t)(gidx * 32 + lane) * CS;
        float4* ovlo = (float4*)(out + (size_t)row_lo * LLEN + t0);
        float4* ovhi = (float4*)(out + (size_t)row_hi * LLEN + t0);
        float ol[4], oh[4];

        // main part 1: k=16..31 (j=8..15), output m = k-16 = 0..15
#pragma unroll
        for (int j = 8; j < 16; j++) {
            float4 f = lw[j];
            int m = (j - 8) * 2;
            u64 w;
            w = step_full2(pack2(f.x, f.y), c, s); unpack2(w, ol[m & 3],       oh[m & 3]);
            w = step_full2(pack2(f.z, f.w), c, s); unpack2(w, ol[(m + 1) & 3], oh[(m + 1) & 3]);
            if ((m & 3) == 2) {
                ovlo[m >> 2] = make_float4(ol[0], ol[1], ol[2], ol[3]);
                ovhi[m >> 2] = make_float4(oh[0], oh[1], oh[2], oh[3]);
            }
        }
        // main part 2: k=32..47 -> float2 idx offset +2 -> j=(k+2)/2 = 17..24, m = k-16 = 16..31
#pragma unroll
        for (int j = 17; j < 25; j++) {
            float4 f = lw[j];
            int m = (j - 17) * 2 + 16;
            u64 w;
            w = step_full2(pack2(f.x, f.y), c, s); unpack2(w, ol[m & 3],       oh[m & 3]);
            w = step_full2(pack2(f.z, f.w), c, s); unpack2(w, ol[(m + 1) & 3], oh[(m + 1) & 3]);
            if ((m & 3) == 2) {
                ovlo[m >> 2] = make_float4(ol[0], ol[1], ol[2], ol[3]);
                ovhi[m >> 2] = make_float4(oh[0], oh[1], oh[2], oh[3]);
            }
        }
    } else {
        // ============ SLOW PATH: first 32 chunks of each row pair ============
        const int t0 = lane * CS;
        const int s0 = (t0 > WARMT) ? (t0 - WARMT) : 0;
        const int f0 = (t0 > (WARMT - WLIGHT)) ? (t0 - (WARMT - WLIGHT)) : 0;
        const float4* xl4 = (const float4*)(x + (size_t)row_lo * LLEN);
        const float4* xh4 = (const float4*)(x + (size_t)row_hi * LLEN);

        for (int q = s0 / 4; q < f0 / 4; q++) {
            float4 a = __ldg(xl4 + q), b = __ldg(xh4 + q);
            step_light2(pack2(a.x, b.x), c, s);
            step_light2(pack2(a.y, b.y), c, s);
            step_light2(pack2(a.z, b.z), c, s);
            step_light2(pack2(a.w, b.w), c, s);
        }
        for (int q = f0 / 4; q < t0 / 4; q++) {
            float4 a = __ldg(xl4 + q), b = __ldg(xh4 + q);
            step_full2(pack2(a.x, b.x), c, s);
            step_full2(pack2(a.y, b.y), c, s);
            step_full2(pack2(a.z, b.z), c, s);
            step_full2(pack2(a.w, b.w), c, s);
        }
        float4* ovlo = (float4*)(out + (size_t)row_lo * LLEN + t0);
        float4* ovhi = (float4*)(out + (size_t)row_hi * LLEN + t0);
        for (int q = t0 / 4, j = 0; q < (t0 + CS) / 4; q++, j++) {
            float4 a = __ldg(xl4 + q), b = __ldg(xh4 + q);
            float4 olo, ohi;
            u64 w;
            w = step_full2(pack2(a.x, b.x), c, s); unpack2(w, olo.x, ohi.x);
            w = step_full2(pack2(a.y, b.y), c, s); unpack2(w, olo.y, ohi.y);
            w = step_full2(pack2(a.z, b.z), c, s); unpack2(w, olo.z, ohi.z);
            w = step_full2(pack2(a.w, b.w), c, s); unpack2(w, olo.w, ohi.w);
            ovlo[j] = olo;
            ovhi[j] = ohi;
        }
    }
}

extern "C" void kernel_launch(void* const* d_in, const int* in_sizes, int n_in,
                              void* d_out, int out_size) {
    (void)in_sizes; (void)n_in; (void)out_size;
    preamp_kernel<<<NBLOCKS, TPB>>>(
        (const float*)d_in[0],  (const float*)d_in[1],  (const float*)d_in[2],
        (const float*)d_in[3],  (const float*)d_in[4],  (const float*)d_in[5],
        (const float*)d_in[6],  (const float*)d_in[7],  (const float*)d_in[8],
        (const float*)d_in[9],  (const float*)d_in[10], (const float*)d_in[11],
        (const float*)d_in[12], (const float*)d_in[13], (float*)d_out);
}

// round 10
// speedup vs baseline: 1.5626x; 1.0017x over previous
#include <cuda_runtime.h>
#include <math.h>

#define LLEN 65536
#define BROWS 64
#define CS 32                   /* samples per chunk */
#define WARMT 16                /* warmup steps */
#define WLIGHT 8                /* light warmup steps */
#define TPB 128                 /* 4 warps per block */
#define NGROUPS 2048            /* 32 row-pairs * 64 groups */
#define NBLOCKS (NGROUPS / 4)   /* 512 */
#define UNION 1040              /* 32*CS + WARMT samples per warp window */
#define TILE_SZ 1104            /* padded: +2 float2 per 32 samples */

typedef unsigned long long u64;

__device__ __forceinline__ u64 pack2(float lo, float hi) {
    u64 r; asm("mov.b64 %0, {%1, %2};" : "=l"(r) : "f"(lo), "f"(hi)); return r;
}
__device__ __forceinline__ void unpack2(u64 v, float& lo, float& hi) {
    asm("mov.b64 {%0, %1}, %2;" : "=f"(lo), "=f"(hi) : "l"(v));
}
__device__ __forceinline__ u64 fma2(u64 a, u64 b, u64 c) {
    u64 d; asm("fma.rn.f32x2 %0, %1, %2, %3;" : "=l"(d) : "l"(a), "l"(b), "l"(c)); return d;
}
__device__ __forceinline__ u64 add2(u64 a, u64 b) {
    u64 d; asm("add.rn.f32x2 %0, %1, %2;" : "=l"(d) : "l"(a), "l"(b)); return d;
}
__device__ __forceinline__ u64 sub2(u64 a, u64 b) {
    u64 d; asm("sub.rn.f32x2 %0, %1, %2;" : "=l"(d) : "l"(a), "l"(b)); return d;
}
__device__ __forceinline__ u64 mul2(u64 a, u64 b) {
    u64 d; asm("mul.rn.f32x2 %0, %1, %2;" : "=l"(d) : "l"(a), "l"(b)); return d;
}
__device__ __forceinline__ u64 tanh2_(u64 v) {
    float lo, hi; unpack2(v, lo, hi);
    float a, b;
    asm("tanh.approx.f32 %0, %1;" : "=f"(a) : "f"(lo));
    asm("tanh.approx.f32 %0, %1;" : "=f"(b) : "f"(hi));
    return pack2(a, b);
}

struct Cf2 {
    u64 pb0a, pb1a, pb2a, pna1a, pna2a;
    u64 pb0b, pb1b, pb2b, pna1b, pna2b;
    u64 GR1, CRc, GZ1, CZc, HR, HZ, GN1, CNc, MH, MB;
    u64 B0, B1, B2, CC, qna1a, qna2a;
    u64 qb0b, qb1b, qb2b, qna1b, qna2b;
    u64 HALF;
};

// DF-II-transposed state: 2 regs per biquad.
struct St2 {
    u64 a1, a2;      // pre bq1
    u64 b1, b2;      // pre bq2
    u64 h;           // GRU
    u64 c1, c2;      // post bq1 (w_out folded; CC re-injected per step)
    u64 d1, d2;      // post bq2
};

__device__ __forceinline__ u64 bq(u64 x, u64 b0, u64 b1, u64 b2,
                                  u64 na1, u64 na2, u64& s1, u64& s2) {
    u64 y = fma2(b0, x, s1);
    s1 = fma2(na1, y, fma2(b1, x, s2));
    s2 = fma2(na2, y, mul2(b2, x));
    return y;
}

__device__ __forceinline__ void step_light2(u64 xi, const Cf2& c, St2& s) {
    u64 v1 = bq(xi, c.pb0a, c.pb1a, c.pb2a, c.pna1a, c.pna2a, s.a1, s.a2);
    u64 v  = bq(v1, c.pb0b, c.pb1b, c.pb2b, c.pna1b, c.pna2b, s.b1, s.b2);

    u64 ur = fma2(v, c.GR1, c.CRc);
    u64 uz = fma2(v, c.GZ1, c.CZc);
    u64 Cn = fma2(v, c.GN1, c.CNc);
    u64 tr = fma2(s.h, c.HR, ur);
    u64 tz = fma2(s.h, c.HZ, uz);
    u64 M2 = fma2(s.h, c.MH, c.MB);
    u64 C2 = add2(Cn, M2);
    u64 t_r = tanh2_(tr);
    u64 t_z = tanh2_(tz);
    u64 z   = fma2(c.HALF, t_z, c.HALF);
    u64 sg  = fma2(t_r, M2, C2);
    u64 n   = tanh2_(sg);
    u64 d   = sub2(s.h, n);
    s.h = fma2(z, d, n);
}

__device__ __forceinline__ u64 step_full2(u64 xi, const Cf2& c, St2& s) {
    step_light2(xi, c, s);
    u64 h = s.h;
    u64 w1 = fma2(c.B0, h, s.c1);
    s.c1 = fma2(c.qna1a, w1, fma2(c.B1, h, add2(s.c2, c.CC)));
    s.c2 = fma2(c.qna2a, w1, mul2(c.B2, h));
    u64 w2 = bq(w1, c.qb0b, c.qb1b, c.qb2b, c.qna1b, c.qna2b, s.d1, s.d2);
    return w2;
}

__global__ void __launch_bounds__(TPB, 4) preamp_kernel(
    const float* __restrict__ x,
    const float* __restrict__ knobs,
    const float* __restrict__ pre_c,
    const float* __restrict__ post_c,
    const float* __restrict__ w_ih,
    const float* __restrict__ w_hh,
    const float* __restrict__ b_ih,
    const float* __restrict__ b_hh,
    const float* __restrict__ w_out,
    const float* __restrict__ b_out,
    const float* __restrict__ kw1,
    const float* __restrict__ kb1,
    const float* __restrict__ kw2,
    const float* __restrict__ kb2,
    float* __restrict__ out)
{
    __shared__ __align__(16) float2 tile[4][TILE_SZ];   // per-warp shared union window

    const int lane = threadIdx.x & 31;
    const int wid  = threadIdx.x >> 5;
    const int G    = blockIdx.x * 4 + wid;   // warp-group 0..2047
    const int rp   = G >> 6;                 // row pair 0..31
    const int gidx = G & 63;                 // group within row
    const int row_lo = rp;
    const int row_hi = rp + 32;

    // ---- Knob MLP, distributed across lanes ----
    // lanes 0-15: hidden unit (lane) for row_lo; lanes 16-31: unit (lane-16) for row_hi.
    float gains[2], biases[2];
    {
        const int unit = lane & 15;
        const float kn = knobs[rp + (lane >> 4) * 32];
        float hh = tanhf(fmaf(kn, kw1[unit], kb1[unit]));
        float p0a = hh * kw2[unit];
        float p1a = hh * kw2[16 + unit];
        // butterfly reduce within each 16-lane half
#pragma unroll
        for (int m = 8; m >= 1; m >>= 1) {
            p0a += __shfl_xor_sync(0xffffffffu, p0a, m);
            p1a += __shfl_xor_sync(0xffffffffu, p1a, m);
        }
        float acc0 = p0a + kb2[0];
        float acc1 = p1a + kb2[1];
        float p0 = 1.0f / (1.0f + expf(-acc0));
        float p1 = 1.0f / (1.0f + expf(-acc1));
        float gain = expf(fmaf(p0, 4.0f, -2.0f));
        float bias = p1 * 0.1f;
        gains[0]  = __shfl_sync(0xffffffffu, gain, 0);
        gains[1]  = __shfl_sync(0xffffffffu, gain, 16);
        biases[0] = __shfl_sync(0xffffffffu, bias, 0);
        biases[1] = __shfl_sync(0xffffffffu, bias, 16);
    }

    // ---- Pack constants ----
    Cf2 c;
    c.pb0a = pack2(pre_c[0], pre_c[0]);    c.pb1a = pack2(pre_c[1], pre_c[1]);
    c.pb2a = pack2(pre_c[2], pre_c[2]);
    c.pna1a = pack2(-pre_c[3], -pre_c[3]); c.pna2a = pack2(-pre_c[4], -pre_c[4]);
    c.pb0b = pack2(pre_c[5], pre_c[5]);    c.pb1b = pack2(pre_c[6], pre_c[6]);
    c.pb2b = pack2(pre_c[7], pre_c[7]);
    c.pna1b = pack2(-pre_c[8], -pre_c[8]); c.pna2b = pack2(-pre_c[9], -pre_c[9]);
    {
        float wih_r = w_ih[0], wih_z = w_ih[1], wih_n = w_ih[2];
        float whh_r = w_hh[0], whh_z = w_hh[1], whh_n = w_hh[2];
        float cr = b_ih[0] + b_hh[0];
        float cz = b_ih[1] + b_hh[1];
        float gr1[2], crc[2], gz1[2], czc[2], gn1[2], cnc[2];
#pragma unroll
        for (int j = 0; j < 2; j++) {
            gr1[j] = 0.5f * wih_r * gains[j]; crc[j] = 0.5f * fmaf(wih_r, biases[j], cr);
            gz1[j] = 0.5f * wih_z * gains[j]; czc[j] = 0.5f * fmaf(wih_z, biases[j], cz);
            gn1[j] = wih_n * gains[j];        cnc[j] = fmaf(wih_n, biases[j], b_ih[2]);
        }
        c.GR1 = pack2(gr1[0], gr1[1]); c.CRc = pack2(crc[0], crc[1]);
        c.GZ1 = pack2(gz1[0], gz1[1]); c.CZc = pack2(czc[0], czc[1]);
        c.GN1 = pack2(gn1[0], gn1[1]); c.CNc = pack2(cnc[0], cnc[1]);
        c.HR = pack2(0.5f * whh_r, 0.5f * whh_r);
        c.HZ = pack2(0.5f * whh_z, 0.5f * whh_z);
        c.MH = pack2(0.5f * whh_n, 0.5f * whh_n);
        c.MB = pack2(0.5f * b_hh[2], 0.5f * b_hh[2]);
    }
    {
        float wout = w_out[0], bout = b_out[0];
        float b0 = post_c[0] * wout, b1 = post_c[1] * wout, b2v = post_c[2] * wout;
        float cc = bout * (post_c[0] + post_c[1] + post_c[2]);
        c.B0 = pack2(b0, b0); c.B1 = pack2(b1, b1); c.B2 = pack2(b2v, b2v);
        c.CC = pack2(cc, cc);
        c.qna1a = pack2(-post_c[3], -post_c[3]); c.qna2a = pack2(-post_c[4], -post_c[4]);
        c.qb0b = pack2(post_c[5], post_c[5]);    c.qb1b = pack2(post_c[6], post_c[6]);
        c.qb2b = pack2(post_c[7], post_c[7]);
        c.qna1b = pack2(-post_c[8], -post_c[8]); c.qna2b = pack2(-post_c[9], -post_c[9]);
    }
    c.HALF = pack2(0.5f, 0.5f);

    St2 s;
    s.a1 = s.a2 = s.b1 = s.b2 = 0ull;
    s.h = 0ull;
    s.c1 = c.CC; s.c2 = 0ull;
    s.d1 = s.d2 = 0ull;

    if (gidx != 0) {
        // ============ FAST PATH ============
        const int base = gidx * 1024 - WARMT;
        const float4* xlo4 = (const float4*)(x + (size_t)row_lo * LLEN + base);
        const float4* xhi4 = (const float4*)(x + (size_t)row_hi * LLEN + base);
        float2* tl = tile[wid];
        // UNION/4 = 260 float4 = 8*32 + 4
#pragma unroll
        for (int rep = 0; rep < 8; rep++) {
            int i = rep * 32 + lane;
            float4 a = __ldg(xlo4 + i);
            float4 b = __ldg(xhi4 + i);
            int p = i * 4;
            int q = p + 2 * (p >> 5);           // +2 float2 per 32 samples
            tl[q + 0] = make_float2(a.x, b.x);
            tl[q + 1] = make_float2(a.y, b.y);
            tl[q + 2] = make_float2(a.z, b.z);
            tl[q + 3] = make_float2(a.w, b.w);
        }
        if (lane < 4) {
            int i = 256 + lane;
            float4 a = __ldg(xlo4 + i);
            float4 b = __ldg(xhi4 + i);
            int p = i * 4;
            int q = p + 2 * (p >> 5);
            tl[q + 0] = make_float2(a.x, b.x);
            tl[q + 1] = make_float2(a.y, b.y);
            tl[q + 2] = make_float2(a.z, b.z);
            tl[q + 3] = make_float2(a.w, b.w);
        }
        __syncwarp();

        // Per-lane window: samples [32*lane, 32*lane+48).
        // float2 idx = 34*lane + k + 2*(k>>5); 16B-aligned base -> LDS.128 pairs.
        const float4* lw = reinterpret_cast<const float4*>(tl + 34 * lane);

        // warmup light: k=0..7 (j = k/2)
#pragma unroll
        for (int j = 0; j < 4; j++) {
            float4 f = lw[j];
            step_light2(pack2(f.x, f.y), c, s);
            step_light2(pack2(f.z, f.w), c, s);
        }
        // warmup full: k=8..15
#pragma unroll
        for (int j = 4; j < 8; j++) {
            float4 f = lw[j];
            step_full2(pack2(f.x, f.y), c, s);
            step_full2(pack2(f.z, f.w), c, s);
        }

        const size_t t0 = (size_t)(gidx * 32 + lane) * CS;
        float4* ovlo = (float4*)(out + (size_t)row_lo * LLEN + t0);
        float4* ovhi = (float4*)(out + (size_t)row_hi * LLEN + t0);
        float ol[4], oh[4];

        // main part 1: k=16..31 (j=8..15), output m = k-16 = 0..15
#pragma unroll
        for (int j = 8; j < 16; j++) {
            float4 f = lw[j];
            int m = (j - 8) * 2;
            u64 w;
            w = step_full2(pack2(f.x, f.y), c, s); unpack2(w, ol[m & 3],       oh[m & 3]);
            w = step_full2(pack2(f.z, f.w), c, s); unpack2(w, ol[(m + 1) & 3], oh[(m + 1) & 3]);
            if ((m & 3) == 2) {
                ovlo[m >> 2] = make_float4(ol[0], ol[1], ol[2], ol[3]);
                ovhi[m >> 2] = make_float4(oh[0], oh[1], oh[2], oh[3]);
            }
        }
        // main part 2: k=32..47 -> float2 idx offset +2 -> j=17..24, m = k-16 = 16..31
#pragma unroll
        for (int j = 17; j < 25; j++) {
            float4 f = lw[j];
            int m = (j - 17) * 2 + 16;
            u64 w;
            w = step_full2(pack2(f.x, f.y), c, s); unpack2(w, ol[m & 3],       oh[m & 3]);
            w = step_full2(pack2(f.z, f.w), c, s); unpack2(w, ol[(m + 1) & 3], oh[(m + 1) & 3]);
            if ((m & 3) == 2) {
                ovlo[m >> 2] = make_float4(ol[0], ol[1], ol[2], ol[3]);
                ovhi[m >> 2] = make_float4(oh[0], oh[1], oh[2], oh[3]);
            }
        }
    } else {
        // ============ SLOW PATH: first 32 chunks of each row pair ============
        const int t0 = lane * CS;
        const int s0 = (t0 > WARMT) ? (t0 - WARMT) : 0;
        const int f0 = (t0 > (WARMT - WLIGHT)) ? (t0 - (WARMT - WLIGHT)) : 0;
        const float4* xl4 = (const float4*)(x + (size_t)row_lo * LLEN);
        const float4* xh4 = (const float4*)(x + (size_t)row_hi * LLEN);

        for (int q = s0 / 4; q < f0 / 4; q++) {
            float4 a = __ldg(xl4 + q), b = __ldg(xh4 + q);
            step_light2(pack2(a.x, b.x), c, s);
            step_light2(pack2(a.y, b.y), c, s);
            step_light2(pack2(a.z, b.z), c, s);
            step_light2(pack2(a.w, b.w), c, s);
        }
        for (int q = f0 / 4; q < t0 / 4; q++) {
            float4 a = __ldg(xl4 + q), b = __ldg(xh4 + q);
            step_full2(pack2(a.x, b.x), c, s);
            step_full2(pack2(a.y, b.y), c, s);
            step_full2(pack2(a.z, b.z), c, s);
            step_full2(pack2(a.w, b.w), c, s);
        }
        float4* ovlo = (float4*)(out + (size_t)row_lo * LLEN + t0);
        float4* ovhi = (float4*)(out + (size_t)row_hi * LLEN + t0);
        for (int q = t0 / 4, j = 0; q < (t0 + CS) / 4; q++, j++) {
            float4 a = __ldg(xl4 + q), b = __ldg(xh4 + q);
            float4 olo, ohi;
            u64 w;
            w = step_full2(pack2(a.x, b.x), c, s); unpack2(w, olo.x, ohi.x);
            w = step_full2(pack2(a.y, b.y), c, s); unpack2(w, olo.y, ohi.y);
            w = step_full2(pack2(a.z, b.z), c, s); unpack2(w, olo.z, ohi.z);
            w = step_full2(pack2(a.w, b.w), c, s); unpack2(w, olo.w, ohi.w);
            ovlo[j] = olo;
            ovhi[j] = ohi;
        }
    }
}

extern "C" void kernel_launch(void* const* d_in, const int* in_sizes, int n_in,
                              void* d_out, int out_size) {
    (void)in_sizes; (void)n_in; (void)out_size;
    preamp_kernel<<<NBLOCKS, TPB>>>(
        (const float*)d_in[0],  (const float*)d_in[1],  (const float*)d_in[2],
        (const float*)d_in[3],  (const float*)d_in[4],  (const float*)d_in[5],
        (const float*)d_in[6],  (const float*)d_in[7],  (const float*)d_in[8],
        (const float*)d_in[9],  (const float*)d_in[10], (const float*)d_in[11],
        (const float*)d_in[12], (const float*)d_in[13], (float*)d_out);
}

// round 11
// speedup vs baseline: 1.7761x; 1.1366x over previous
#include <cuda_runtime.h>
#include <math.h>

#define LLEN 65536
#define BROWS 64
#define CS 32                   /* samples per chunk */
#define WARMT 16                /* warmup steps */
#define WLIGHT 8                /* light warmup steps */
#define TPB 64                  /* 2 warps per block (pure packing choice) */
#define NGROUPS 2048            /* 32 row-pairs * 64 groups */
#define NBLOCKS (NGROUPS / 2)   /* 1024 */
#define UNION 1040              /* 32*CS + WARMT samples per warp window */
#define TILE_SZ 1104            /* padded: +2 float2 per 32 samples */

typedef unsigned long long u64;

__device__ __forceinline__ u64 pack2(float lo, float hi) {
    u64 r; asm("mov.b64 %0, {%1, %2};" : "=l"(r) : "f"(lo), "f"(hi)); return r;
}
__device__ __forceinline__ void unpack2(u64 v, float& lo, float& hi) {
    asm("mov.b64 {%0, %1}, %2;" : "=f"(lo), "=f"(hi) : "l"(v));
}
__device__ __forceinline__ u64 fma2(u64 a, u64 b, u64 c) {
    u64 d; asm("fma.rn.f32x2 %0, %1, %2, %3;" : "=l"(d) : "l"(a), "l"(b), "l"(c)); return d;
}
__device__ __forceinline__ u64 add2(u64 a, u64 b) {
    u64 d; asm("add.rn.f32x2 %0, %1, %2;" : "=l"(d) : "l"(a), "l"(b)); return d;
}
__device__ __forceinline__ u64 sub2(u64 a, u64 b) {
    u64 d; asm("sub.rn.f32x2 %0, %1, %2;" : "=l"(d) : "l"(a), "l"(b)); return d;
}
__device__ __forceinline__ u64 mul2(u64 a, u64 b) {
    u64 d; asm("mul.rn.f32x2 %0, %1, %2;" : "=l"(d) : "l"(a), "l"(b)); return d;
}
__device__ __forceinline__ u64 tanh2_(u64 v) {
    float lo, hi; unpack2(v, lo, hi);
    float a, b;
    asm("tanh.approx.f32 %0, %1;" : "=f"(a) : "f"(lo));
    asm("tanh.approx.f32 %0, %1;" : "=f"(b) : "f"(hi));
    return pack2(a, b);
}

struct Cf2 {
    u64 pb0a, pb1a, pb2a, pna1a, pna2a;
    u64 pb0b, pb1b, pb2b, pna1b, pna2b;
    u64 GR1, CRc, GZ1, CZc, HR, HZ, GN1, CNc, MH, MB;
    u64 B0, B1, B2, CC, qna1a, qna2a;
    u64 qb0b, qb1b, qb2b, qna1b, qna2b;
    u64 HALF;
};

// DF-II-transposed state: 2 regs per biquad.
struct St2 {
    u64 a1, a2;      // pre bq1
    u64 b1, b2;      // pre bq2
    u64 h;           // GRU
    u64 c1, c2;      // post bq1 (w_out folded; CC re-injected per step)
    u64 d1, d2;      // post bq2
};

__device__ __forceinline__ u64 bq(u64 x, u64 b0, u64 b1, u64 b2,
                                  u64 na1, u64 na2, u64& s1, u64& s2) {
    u64 y = fma2(b0, x, s1);
    s1 = fma2(na1, y, fma2(b1, x, s2));
    s2 = fma2(na2, y, mul2(b2, x));
    return y;
}

__device__ __forceinline__ void step_light2(u64 xi, const Cf2& c, St2& s) {
    u64 v1 = bq(xi, c.pb0a, c.pb1a, c.pb2a, c.pna1a, c.pna2a, s.a1, s.a2);
    u64 v  = bq(v1, c.pb0b, c.pb1b, c.pb2b, c.pna1b, c.pna2b, s.b1, s.b2);

    u64 ur = fma2(v, c.GR1, c.CRc);
    u64 uz = fma2(v, c.GZ1, c.CZc);
    u64 Cn = fma2(v, c.GN1, c.CNc);
    u64 tr = fma2(s.h, c.HR, ur);
    u64 tz = fma2(s.h, c.HZ, uz);
    u64 M2 = fma2(s.h, c.MH, c.MB);
    u64 C2 = add2(Cn, M2);
    u64 t_r = tanh2_(tr);
    u64 t_z = tanh2_(tz);
    u64 z   = fma2(c.HALF, t_z, c.HALF);
    u64 sg  = fma2(t_r, M2, C2);
    u64 n   = tanh2_(sg);
    u64 d   = sub2(s.h, n);
    s.h = fma2(z, d, n);
}

__device__ __forceinline__ u64 step_full2(u64 xi, const Cf2& c, St2& s) {
    step_light2(xi, c, s);
    u64 h = s.h;
    u64 w1 = fma2(c.B0, h, s.c1);
    s.c1 = fma2(c.qna1a, w1, fma2(c.B1, h, add2(s.c2, c.CC)));
    s.c2 = fma2(c.qna2a, w1, mul2(c.B2, h));
    u64 w2 = bq(w1, c.qb0b, c.qb1b, c.qb2b, c.qna1b, c.qna2b, s.d1, s.d2);
    return w2;
}

__global__ void __launch_bounds__(TPB, 8) preamp_kernel(
    const float* __restrict__ x,
    const float* __restrict__ knobs,
    const float* __restrict__ pre_c,
    const float* __restrict__ post_c,
    const float* __restrict__ w_ih,
    const float* __restrict__ w_hh,
    const float* __restrict__ b_ih,
    const float* __restrict__ b_hh,
    const float* __restrict__ w_out,
    const float* __restrict__ b_out,
    const float* __restrict__ kw1,
    const float* __restrict__ kb1,
    const float* __restrict__ kw2,
    const float* __restrict__ kb2,
    float* __restrict__ out)
{
    __shared__ __align__(16) float2 tile[2][TILE_SZ];   // per-warp shared union window

    const int lane = threadIdx.x & 31;
    const int wid  = threadIdx.x >> 5;
    const int G    = blockIdx.x * 2 + wid;   // warp-group 0..2047
    const int rp   = G >> 6;                 // row pair 0..31
    const int gidx = G & 63;                 // group within row
    const int row_lo = rp;
    const int row_hi = rp + 32;

    // ---- Knob MLP, distributed across lanes ----
    float gains[2], biases[2];
    {
        const int unit = lane & 15;
        const float kn = knobs[rp + (lane >> 4) * 32];
        float hh = tanhf(fmaf(kn, kw1[unit], kb1[unit]));
        float p0a = hh * kw2[unit];
        float p1a = hh * kw2[16 + unit];
#pragma unroll
        for (int m = 8; m >= 1; m >>= 1) {
            p0a += __shfl_xor_sync(0xffffffffu, p0a, m);
            p1a += __shfl_xor_sync(0xffffffffu, p1a, m);
        }
        float acc0 = p0a + kb2[0];
        float acc1 = p1a + kb2[1];
        float p0 = 1.0f / (1.0f + expf(-acc0));
        float p1 = 1.0f / (1.0f + expf(-acc1));
        float gain = expf(fmaf(p0, 4.0f, -2.0f));
        float bias = p1 * 0.1f;
        gains[0]  = __shfl_sync(0xffffffffu, gain, 0);
        gains[1]  = __shfl_sync(0xffffffffu, gain, 16);
        biases[0] = __shfl_sync(0xffffffffu, bias, 0);
        biases[1] = __shfl_sync(0xffffffffu, bias, 16);
    }

    // ---- Pack constants ----
    Cf2 c;
    c.pb0a = pack2(pre_c[0], pre_c[0]);    c.pb1a = pack2(pre_c[1], pre_c[1]);
    c.pb2a = pack2(pre_c[2], pre_c[2]);
    c.pna1a = pack2(-pre_c[3], -pre_c[3]); c.pna2a = pack2(-pre_c[4], -pre_c[4]);
    c.pb0b = pack2(pre_c[5], pre_c[5]);    c.pb1b = pack2(pre_c[6], pre_c[6]);
    c.pb2b = pack2(pre_c[7], pre_c[7]);
    c.pna1b = pack2(-pre_c[8], -pre_c[8]); c.pna2b = pack2(-pre_c[9], -pre_c[9]);
    {
        float wih_r = w_ih[0], wih_z = w_ih[1], wih_n = w_ih[2];
        float whh_r = w_hh[0], whh_z = w_hh[1], whh_n = w_hh[2];
        float cr = b_ih[0] + b_hh[0];
        float cz = b_ih[1] + b_hh[1];
        float gr1[2], crc[2], gz1[2], czc[2], gn1[2], cnc[2];
#pragma unroll
        for (int j = 0; j < 2; j++) {
            gr1[j] = 0.5f * wih_r * gains[j]; crc[j] = 0.5f * fmaf(wih_r, biases[j], cr);
            gz1[j] = 0.5f * wih_z * gains[j]; czc[j] = 0.5f * fmaf(wih_z, biases[j], cz);
            gn1[j] = wih_n * gains[j];        cnc[j] = fmaf(wih_n, biases[j], b_ih[2]);
        }
        c.GR1 = pack2(gr1[0], gr1[1]); c.CRc = pack2(crc[0], crc[1]);
        c.GZ1 = pack2(gz1[0], gz1[1]); c.CZc = pack2(czc[0], czc[1]);
        c.GN1 = pack2(gn1[0], gn1[1]); c.CNc = pack2(cnc[0], cnc[1]);
        c.HR = pack2(0.5f * whh_r, 0.5f * whh_r);
        c.HZ = pack2(0.5f * whh_z, 0.5f * whh_z);
        c.MH = pack2(0.5f * whh_n, 0.5f * whh_n);
        c.MB = pack2(0.5f * b_hh[2], 0.5f * b_hh[2]);
    }
    {
        float wout = w_out[0], bout = b_out[0];
        float b0 = post_c[0] * wout, b1 = post_c[1] * wout, b2v = post_c[2] * wout;
        float cc = bout * (post_c[0] + post_c[1] + post_c[2]);
        c.B0 = pack2(b0, b0); c.B1 = pack2(b1, b1); c.B2 = pack2(b2v, b2v);
        c.CC = pack2(cc, cc);
        c.qna1a = pack2(-post_c[3], -post_c[3]); c.qna2a = pack2(-post_c[4], -post_c[4]);
        c.qb0b = pack2(post_c[5], post_c[5]);    c.qb1b = pack2(post_c[6], post_c[6]);
        c.qb2b = pack2(post_c[7], post_c[7]);
        c.qna1b = pack2(-post_c[8], -post_c[8]); c.qna2b = pack2(-post_c[9], -post_c[9]);
    }
    c.HALF = pack2(0.5f, 0.5f);

    St2 s;
    s.a1 = s.a2 = s.b1 = s.b2 = 0ull;
    s.h = 0ull;
    s.c1 = c.CC; s.c2 = 0ull;
    s.d1 = s.d2 = 0ull;

    if (gidx != 0) {
        // ============ FAST PATH ============
        const int base = gidx * 1024 - WARMT;
        const float4* xlo4 = (const float4*)(x + (size_t)row_lo * LLEN + base);
        const float4* xhi4 = (const float4*)(x + (size_t)row_hi * LLEN + base);
        float2* tl = tile[wid];
#pragma unroll
        for (int rep = 0; rep < 8; rep++) {
            int i = rep * 32 + lane;
            float4 a = __ldg(xlo4 + i);
            float4 b = __ldg(xhi4 + i);
            int p = i * 4;
            int q = p + 2 * (p >> 5);           // +2 float2 per 32 samples
            tl[q + 0] = make_float2(a.x, b.x);
            tl[q + 1] = make_float2(a.y, b.y);
            tl[q + 2] = make_float2(a.z, b.z);
            tl[q + 3] = make_float2(a.w, b.w);
        }
        if (lane < 4) {
            int i = 256 + lane;
            float4 a = __ldg(xlo4 + i);
            float4 b = __ldg(xhi4 + i);
            int p = i * 4;
            int q = p + 2 * (p >> 5);
            tl[q + 0] = make_float2(a.x, b.x);
            tl[q + 1] = make_float2(a.y, b.y);
            tl[q + 2] = make_float2(a.z, b.z);
            tl[q + 3] = make_float2(a.w, b.w);
        }
        __syncwarp();

        // Per-lane window: samples [32*lane, 32*lane+48).
        // float2 idx = 34*lane + k + 2*(k>>5); 16B-aligned base -> LDS.128 pairs.
        const float4* lw = reinterpret_cast<const float4*>(tl + 34 * lane);

        // warmup light: k=0..7
#pragma unroll
        for (int j = 0; j < 4; j++) {
            float4 f = lw[j];
            step_light2(pack2(f.x, f.y), c, s);
            step_light2(pack2(f.z, f.w), c, s);
        }
        // warmup full: k=8..15
#pragma unroll
        for (int j = 4; j < 8; j++) {
            float4 f = lw[j];
            step_full2(pack2(f.x, f.y), c, s);
            step_full2(pack2(f.z, f.w), c, s);
        }

        const size_t t0 = (size_t)(gidx * 32 + lane) * CS;
        float4* ovlo = (float4*)(out + (size_t)row_lo * LLEN + t0);
        float4* ovhi = (float4*)(out + (size_t)row_hi * LLEN + t0);
        float ol[4], oh[4];

        // main part 1: k=16..31 (j=8..15), output m = k-16 = 0..15
#pragma unroll
        for (int j = 8; j < 16; j++) {
            float4 f = lw[j];
            int m = (j - 8) * 2;
            u64 w;
            w = step_full2(pack2(f.x, f.y), c, s); unpack2(w, ol[m & 3],       oh[m & 3]);
            w = step_full2(pack2(f.z, f.w), c, s); unpack2(w, ol[(m + 1) & 3], oh[(m + 1) & 3]);
            if ((m & 3) == 2) {
                ovlo[m >> 2] = make_float4(ol[0], ol[1], ol[2], ol[3]);
                ovhi[m >> 2] = make_float4(oh[0], oh[1], oh[2], oh[3]);
            }
        }
        // main part 2: k=32..47 -> float2 idx offset +2 -> j=17..24, m = 16..31
#pragma unroll
        for (int j = 17; j < 25; j++) {
            float4 f = lw[j];
            int m = (j - 17) * 2 + 16;
            u64 w;
            w = step_full2(pack2(f.x, f.y), c, s); unpack2(w, ol[m & 3],       oh[m & 3]);
            w = step_full2(pack2(f.z, f.w), c, s); unpack2(w, ol[(m + 1) & 3], oh[(m + 1) & 3]);
            if ((m & 3) == 2) {
                ovlo[m >> 2] = make_float4(ol[0], ol[1], ol[2], ol[3]);
                ovhi[m >> 2] = make_float4(oh[0], oh[1], oh[2], oh[3]);
            }
        }
    } else {
        // ============ SLOW PATH: first 32 chunks of each row pair ============
        const int t0 = lane * CS;
        const int s0 = (t0 > WARMT) ? (t0 - WARMT) : 0;
        const int f0 = (t0 > (WARMT - WLIGHT)) ? (t0 - (WARMT - WLIGHT)) : 0;
        const float4* xl4 = (const float4*)(x + (size_t)row_lo * LLEN);
        const float4* xh4 = (const float4*)(x + (size_t)row_hi * LLEN);

        for (int q = s0 / 4; q < f0 / 4; q++) {
            float4 a = __ldg(xl4 + q), b = __ldg(xh4 + q);
            step_light2(pack2(a.x, b.x), c, s);
            step_light2(pack2(a.y, b.y), c, s);
            step_light2(pack2(a.z, b.z), c, s);
            step_light2(pack2(a.w, b.w), c, s);
        }
        for (int q = f0 / 4; q < t0 / 4; q++) {
            float4 a = __ldg(xl4 + q), b = __ldg(xh4 + q);
            step_full2(pack2(a.x, b.x), c, s);
            step_full2(pack2(a.y, b.y), c, s);
            step_full2(pack2(a.z, b.z), c, s);
            step_full2(pack2(a.w, b.w), c, s);
        }
        float4* ovlo = (float4*)(out + (size_t)row_lo * LLEN + t0);
        float4* ovhi = (float4*)(out + (size_t)row_hi * LLEN + t0);
        for (int q = t0 / 4, j = 0; q < (t0 + CS) / 4; q++, j++) {
            float4 a = __ldg(xl4 + q), b = __ldg(xh4 + q);
            float4 olo, ohi;
            u64 w;
            w = step_full2(pack2(a.x, b.x), c, s); unpack2(w, olo.x, ohi.x);
            w = step_full2(pack2(a.y, b.y), c, s); unpack2(w, olo.y, ohi.y);
            w = step_full2(pack2(a.z, b.z), c, s); unpack2(w, olo.z, ohi.z);
            w = step_full2(pack2(a.w, b.w), c, s); unpack2(w, olo.w, ohi.w);
            ovlo[j] = olo;
            ovhi[j] = ohi;
        }
    }
}

extern "C" void kernel_launch(void* const* d_in, const int* in_sizes, int n_in,
                              void* d_out, int out_size) {
    (void)in_sizes; (void)n_in; (void)out_size;
    preamp_kernel<<<NBLOCKS, TPB>>>(
        (const float*)d_in[0],  (const float*)d_in[1],  (const float*)d_in[2],
        (const float*)d_in[3],  (const float*)d_in[4],  (const float*)d_in[5],
        (const float*)d_in[6],  (const float*)d_in[7],  (const float*)d_in[8],
        (const float*)d_in[9],  (const float*)d_in[10], (const float*)d_in[11],
        (const float*)d_in[12], (const float*)d_in[13], (float*)d_out);
}